// round 2
// baseline (speedup 1.0000x reference)
#include <cuda_runtime.h>

#define DM 768
#define NH 12
#define DKH 64
#define SQ 4096
#define NB 2
#define NT (NB * SQ)   // 8192 tokens

// Scratch (allocation-free rule: __device__ globals)
__device__ float g_q[(size_t)NT * DM];
__device__ float g_k[(size_t)NT * DM];
__device__ float g_v[(size_t)NT * DM];
__device__ float g_att[(size_t)NT * DM];

__device__ __forceinline__ float redmax16(float v) {
    v = fmaxf(v, __shfl_xor_sync(0xffffffffu, v, 1));
    v = fmaxf(v, __shfl_xor_sync(0xffffffffu, v, 2));
    v = fmaxf(v, __shfl_xor_sync(0xffffffffu, v, 4));
    v = fmaxf(v, __shfl_xor_sync(0xffffffffu, v, 8));
    return v;
}
__device__ __forceinline__ float redsum16(float v) {
    v += __shfl_xor_sync(0xffffffffu, v, 1);
    v += __shfl_xor_sync(0xffffffffu, v, 2);
    v += __shfl_xor_sync(0xffffffffu, v, 4);
    v += __shfl_xor_sync(0xffffffffu, v, 8);
    return v;
}

// ---------------------------------------------------------------------------
// C[M,N] = A[M,K] @ W[N,K]^T + bias[N]   (torch Linear), M=8192, N=K=768
// 64x64 tile, BK=16, 256 threads, 4x4 per thread, float4 smem reads.
// ---------------------------------------------------------------------------
__global__ __launch_bounds__(256)
void gemm_bias_kernel(const float* __restrict__ A, const float* __restrict__ W,
                      const float* __restrict__ bias, float* __restrict__ C)
{
    __shared__ float As[16][68];   // As[k][m], stride 68 -> 16B-aligned float4 rows
    __shared__ float Ws[16][68];   // Ws[k][n]
    const int K = DM, N = DM;
    const int tid = threadIdx.x;
    const int tx = tid & 15, ty = tid >> 4;
    const int m0 = blockIdx.y << 6, n0 = blockIdx.x << 6;

    const int lr = tid >> 2;          // 0..63 row within tile
    const int lc = (tid & 3) << 2;    // 0,4,8,12 col within BK
    const float* Ap = A + (size_t)(m0 + lr) * K + lc;
    const float* Wp = W + (size_t)(n0 + lr) * K + lc;

    float acc[4][4] = {};

    for (int k0 = 0; k0 < K; k0 += 16) {
        float4 av = *(const float4*)(Ap + k0);
        float4 wv = *(const float4*)(Wp + k0);
        __syncthreads();   // previous tile's compute done before overwrite
        As[lc + 0][lr] = av.x; As[lc + 1][lr] = av.y;
        As[lc + 2][lr] = av.z; As[lc + 3][lr] = av.w;
        Ws[lc + 0][lr] = wv.x; Ws[lc + 1][lr] = wv.y;
        Ws[lc + 2][lr] = wv.z; Ws[lc + 3][lr] = wv.w;
        __syncthreads();
        #pragma unroll
        for (int kk = 0; kk < 16; kk++) {
            float4 a4 = *(const float4*)&As[kk][ty << 2];
            float4 w4 = *(const float4*)&Ws[kk][tx << 2];
            float a[4] = {a4.x, a4.y, a4.z, a4.w};
            float w[4] = {w4.x, w4.y, w4.z, w4.w};
            #pragma unroll
            for (int i = 0; i < 4; i++)
                #pragma unroll
                for (int j = 0; j < 4; j++)
                    acc[i][j] = fmaf(a[i], w[j], acc[i][j]);
        }
    }

    float4 b4 = *(const float4*)(bias + n0 + (tx << 2));
    float bj[4] = {b4.x, b4.y, b4.z, b4.w};
    #pragma unroll
    for (int i = 0; i < 4; i++) {
        float4 r;
        r.x = acc[i][0] + bj[0];
        r.y = acc[i][1] + bj[1];
        r.z = acc[i][2] + bj[2];
        r.w = acc[i][3] + bj[3];
        *(float4*)&C[(size_t)(m0 + (ty << 2) + i) * N + n0 + (tx << 2)] = r;
    }
}

// ---------------------------------------------------------------------------
// Flash attention, fp32. One CTA = 64 queries of one (b,h).
// smem: Qs[d][r] (Q^T, pre-scaled), Ks[d][c] (K^T), Ps[c][r] (P^T), Vs[c][d].
// All inner loops: 2x LDS.128 + 16 FFMA per step -> FFMA-bound.
// ---------------------------------------------------------------------------
#define FL_SMEM ((3 * 64 * 68 + 64 * 64) * 4)

__global__ __launch_bounds__(256)
void flash_kernel(const float* __restrict__ q, const float* __restrict__ k,
                  const float* __restrict__ v, float* __restrict__ o)
{
    extern __shared__ float sm[];
    float (*Qs)[68] = (float(*)[68])sm;                  // [64][68]
    float (*Ks)[68] = (float(*)[68])(sm + 64 * 68);      // [64][68]
    float (*Ps)[68] = (float(*)[68])(sm + 2 * 64 * 68);  // [64][68]
    float (*Vs)[64] = (float(*)[64])(sm + 3 * 64 * 68);  // [64][64]

    const int tid = threadIdx.x;
    const int tx = tid & 15, ty = tid >> 4;
    const int bh = blockIdx.y;
    const int b = bh / NH, h = bh - b * NH;
    const int q0 = blockIdx.x << 6;

    const float* qb = q + (size_t)b * SQ * DM + (size_t)h * DKH;
    const float* kb = k + (size_t)b * SQ * DM + (size_t)h * DKH;
    const float* vb = v + (size_t)b * SQ * DM + (size_t)h * DKH;
    float* ob       = o + (size_t)b * SQ * DM + (size_t)h * DKH;

    const int lr = tid >> 4;          // 0..15
    const int lc = (tid & 15) << 2;   // 0..60

    // Load Q tile transposed, pre-scaled by 1/sqrt(dk)=0.125
    #pragma unroll
    for (int it = 0; it < 4; it++) {
        int r = lr + it * 16;
        float4 t = *(const float4*)(qb + (size_t)(q0 + r) * DM + lc);
        Qs[lc + 0][r] = t.x * 0.125f;
        Qs[lc + 1][r] = t.y * 0.125f;
        Qs[lc + 2][r] = t.z * 0.125f;
        Qs[lc + 3][r] = t.w * 0.125f;
    }

    float m_i[4], l_i[4], oacc[4][4];
    #pragma unroll
    for (int i = 0; i < 4; i++) {
        m_i[i] = -1e30f; l_i[i] = 0.f;
        #pragma unroll
        for (int j = 0; j < 4; j++) oacc[i][j] = 0.f;
    }

    for (int kv0 = 0; kv0 < SQ; kv0 += 64) {
        __syncthreads();   // previous PV readers done before K/V/P overwrite
        #pragma unroll
        for (int it = 0; it < 4; it++) {
            int r = lr + it * 16;
            float4 tk = *(const float4*)(kb + (size_t)(kv0 + r) * DM + lc);
            Ks[lc + 0][r] = tk.x; Ks[lc + 1][r] = tk.y;
            Ks[lc + 2][r] = tk.z; Ks[lc + 3][r] = tk.w;
            float4 tv = *(const float4*)(vb + (size_t)(kv0 + r) * DM + lc);
            *(float4*)&Vs[r][lc] = tv;
        }
        __syncthreads();

        // S = Q K^T (scaled)
        float s[4][4] = {};
        #pragma unroll 4
        for (int d = 0; d < 64; d++) {
            float4 a4 = *(const float4*)&Qs[d][ty << 2];
            float4 k4 = *(const float4*)&Ks[d][tx << 2];
            float a[4] = {a4.x, a4.y, a4.z, a4.w};
            float w[4] = {k4.x, k4.y, k4.z, k4.w};
            #pragma unroll
            for (int i = 0; i < 4; i++)
                #pragma unroll
                for (int j = 0; j < 4; j++)
                    s[i][j] = fmaf(a[i], w[j], s[i][j]);
        }

        // Online softmax
        #pragma unroll
        for (int i = 0; i < 4; i++) {
            float mx = fmaxf(fmaxf(s[i][0], s[i][1]), fmaxf(s[i][2], s[i][3]));
            mx = redmax16(mx);
            float mnew = fmaxf(m_i[i], mx);
            float alpha = __expf(m_i[i] - mnew);
            m_i[i] = mnew;
            float rsum = 0.f;
            #pragma unroll
            for (int j = 0; j < 4; j++) {
                float p = __expf(s[i][j] - mnew);
                s[i][j] = p;
                rsum += p;
            }
            rsum = redsum16(rsum);
            l_i[i] = l_i[i] * alpha + rsum;
            #pragma unroll
            for (int j = 0; j < 4; j++) oacc[i][j] *= alpha;
        }

        // Stage P transposed: Ps[c][r]
        #pragma unroll
        for (int j = 0; j < 4; j++)
            #pragma unroll
            for (int i = 0; i < 4; i++)
                Ps[(tx << 2) + j][(ty << 2) + i] = s[i][j];
        __syncthreads();

        // O += P V
        #pragma unroll 4
        for (int c = 0; c < 64; c++) {
            float4 p4 = *(const float4*)&Ps[c][ty << 2];
            float4 v4 = *(const float4*)&Vs[c][tx << 2];
            float p[4]  = {p4.x, p4.y, p4.z, p4.w};
            float vv[4] = {v4.x, v4.y, v4.z, v4.w};
            #pragma unroll
            for (int i = 0; i < 4; i++)
                #pragma unroll
                for (int j = 0; j < 4; j++)
                    oacc[i][j] = fmaf(p[i], vv[j], oacc[i][j]);
        }
    }

    // Normalize + write combined layout (B,S,H*dk) directly
    #pragma unroll
    for (int i = 0; i < 4; i++) {
        float inv = 1.0f / l_i[i];
        float4 r;
        r.x = oacc[i][0] * inv; r.y = oacc[i][1] * inv;
        r.z = oacc[i][2] * inv; r.w = oacc[i][3] * inv;
        *(float4*)(ob + (size_t)(q0 + (ty << 2) + i) * DM + (tx << 2)) = r;
    }
}

// ---------------------------------------------------------------------------
extern "C" void kernel_launch(void* const* d_in, const int* in_sizes, int n_in,
                              void* d_out, int out_size)
{
    const float* Q  = (const float*)d_in[0];
    const float* K  = (const float*)d_in[1];
    const float* V  = (const float*)d_in[2];
    const float* Wq = (const float*)d_in[3];
    const float* bq = (const float*)d_in[4];
    const float* Wk = (const float*)d_in[5];
    const float* bk = (const float*)d_in[6];
    const float* Wv = (const float*)d_in[7];
    const float* bv = (const float*)d_in[8];
    const float* Wo = (const float*)d_in[9];
    const float* bo = (const float*)d_in[10];
    float* out = (float*)d_out;

    float *gq, *gk, *gv, *ga;
    cudaGetSymbolAddress((void**)&gq, g_q);
    cudaGetSymbolAddress((void**)&gk, g_k);
    cudaGetSymbolAddress((void**)&gv, g_v);
    cudaGetSymbolAddress((void**)&ga, g_att);

    cudaFuncSetAttribute(flash_kernel,
                         cudaFuncAttributeMaxDynamicSharedMemorySize, FL_SMEM);

    dim3 gg(DM / 64, NT / 64);   // (12, 128)
    gemm_bias_kernel<<<gg, 256>>>(Q, Wq, bq, gq);
    gemm_bias_kernel<<<gg, 256>>>(K, Wk, bk, gk);
    gemm_bias_kernel<<<gg, 256>>>(V, Wv, bv, gv);

    dim3 fg(SQ / 64, NB * NH);   // (64, 24)
    flash_kernel<<<fg, 256, FL_SMEM>>>(gq, gk, gv, ga);

    gemm_bias_kernel<<<gg, 256>>>(ga, Wo, bo, out);
}

// round 5
// speedup vs baseline: 1.1321x; 1.1321x over previous
#include <cuda_runtime.h>

#define DM 768
#define NH 12
#define DKH 64
#define SQ 4096
#define NB 2
#define NT (NB * SQ)   // 8192 tokens

// Scratch (allocation-free rule: __device__ globals)
__device__ float g_q[(size_t)NT * DM];
__device__ float g_k[(size_t)NT * DM];
__device__ float g_v[(size_t)NT * DM];
__device__ float g_att[(size_t)NT * DM];

__device__ __forceinline__ float redmax16(float v) {
    v = fmaxf(v, __shfl_xor_sync(0xffffffffu, v, 1));
    v = fmaxf(v, __shfl_xor_sync(0xffffffffu, v, 2));
    v = fmaxf(v, __shfl_xor_sync(0xffffffffu, v, 4));
    v = fmaxf(v, __shfl_xor_sync(0xffffffffu, v, 8));
    return v;
}
__device__ __forceinline__ float redsum16(float v) {
    v += __shfl_xor_sync(0xffffffffu, v, 1);
    v += __shfl_xor_sync(0xffffffffu, v, 2);
    v += __shfl_xor_sync(0xffffffffu, v, 4);
    v += __shfl_xor_sync(0xffffffffu, v, 8);
    return v;
}

// ---------------------------------------------------------------------------
// C[M,N] = A[M,K] @ W[N,K]^T + bias[N]   (torch Linear), M=8192, N=K=768
// 128x128 tile, BK=16, 256 threads, 8x8 per thread (16 FFMA per LDS.128).
// ---------------------------------------------------------------------------
__global__ __launch_bounds__(256)
void gemm_bias_kernel(const float* __restrict__ A, const float* __restrict__ W,
                      const float* __restrict__ bias, float* __restrict__ C)
{
    __shared__ float As[16][132];   // As[k][m]
    __shared__ float Ws[16][132];   // Ws[k][n]
    const int tid = threadIdx.x;
    const int tx = tid & 15, ty = tid >> 4;
    const int m0 = blockIdx.y << 7, n0 = blockIdx.x << 7;

    const int lr = tid >> 2;          // 0..63
    const int lc = (tid & 3) << 2;    // 0,4,8,12
    const float* Ap = A + (size_t)(m0 + lr) * DM + lc;
    const float* Wp = W + (size_t)(n0 + lr) * DM + lc;

    float acc[8][8] = {};

    for (int k0 = 0; k0 < DM; k0 += 16) {
        float4 av0 = *(const float4*)(Ap + k0);
        float4 av1 = *(const float4*)(Ap + (size_t)64 * DM + k0);
        float4 wv0 = *(const float4*)(Wp + k0);
        float4 wv1 = *(const float4*)(Wp + (size_t)64 * DM + k0);
        __syncthreads();
        As[lc + 0][lr] = av0.x; As[lc + 1][lr] = av0.y;
        As[lc + 2][lr] = av0.z; As[lc + 3][lr] = av0.w;
        As[lc + 0][lr + 64] = av1.x; As[lc + 1][lr + 64] = av1.y;
        As[lc + 2][lr + 64] = av1.z; As[lc + 3][lr + 64] = av1.w;
        Ws[lc + 0][lr] = wv0.x; Ws[lc + 1][lr] = wv0.y;
        Ws[lc + 2][lr] = wv0.z; Ws[lc + 3][lr] = wv0.w;
        Ws[lc + 0][lr + 64] = wv1.x; Ws[lc + 1][lr + 64] = wv1.y;
        Ws[lc + 2][lr + 64] = wv1.z; Ws[lc + 3][lr + 64] = wv1.w;
        __syncthreads();
        #pragma unroll
        for (int kk = 0; kk < 16; kk++) {
            float4 fa0 = *(const float4*)&As[kk][ty << 3];
            float4 fa1 = *(const float4*)&As[kk][(ty << 3) + 4];
            float4 fb0 = *(const float4*)&Ws[kk][tx << 2];
            float4 fb1 = *(const float4*)&Ws[kk][64 + (tx << 2)];
            float a[8] = {fa0.x, fa0.y, fa0.z, fa0.w, fa1.x, fa1.y, fa1.z, fa1.w};
            float b[8] = {fb0.x, fb0.y, fb0.z, fb0.w, fb1.x, fb1.y, fb1.z, fb1.w};
            #pragma unroll
            for (int i = 0; i < 8; i++)
                #pragma unroll
                for (int j = 0; j < 8; j++)
                    acc[i][j] = fmaf(a[i], b[j], acc[i][j]);
        }
    }

    float4 bb0 = *(const float4*)(bias + n0 + (tx << 2));
    float4 bb1 = *(const float4*)(bias + n0 + 64 + (tx << 2));
    #pragma unroll
    for (int i = 0; i < 8; i++) {
        size_t row = (size_t)(m0 + (ty << 3) + i) * DM;
        float4 r0, r1;
        r0.x = acc[i][0] + bb0.x; r0.y = acc[i][1] + bb0.y;
        r0.z = acc[i][2] + bb0.z; r0.w = acc[i][3] + bb0.w;
        r1.x = acc[i][4] + bb1.x; r1.y = acc[i][5] + bb1.y;
        r1.z = acc[i][6] + bb1.z; r1.w = acc[i][7] + bb1.w;
        *(float4*)&C[row + n0 + (tx << 2)] = r0;
        *(float4*)&C[row + n0 + 64 + (tx << 2)] = r1;
    }
}

// ---------------------------------------------------------------------------
// Flash attention, fp32. One CTA = 128 queries of one (b,h), KV in 128 blocks.
// Per-thread 8 rows (ty) x 8 kv-cols {tx*4+j, 64+tx*4+j}; output 8 rows x 4 d.
// Ps kept row-major: PV reads of P broadcast across tx (1 wavefront/LDS.128).
// ---------------------------------------------------------------------------
#define QS_F 0
#define KS_F (64 * 132)
#define VS_F (2 * 64 * 132)
#define PS_F (2 * 64 * 132 + 128 * 68)
#define FL_SMEM ((2 * 64 * 132 + 128 * 68 + 128 * 128) * 4)

__global__ __launch_bounds__(256)
void flash_kernel(const float* __restrict__ q, const float* __restrict__ k,
                  const float* __restrict__ v, float* __restrict__ o)
{
    extern __shared__ float sm[];
    float (*Qs)[132] = (float(*)[132])(sm + QS_F);   // [64][132]  Q^T scaled
    float (*Ks)[132] = (float(*)[132])(sm + KS_F);   // [64][132]  K^T
    float (*Vs)[68]  = (float(*)[68])(sm + VS_F);    // [128][68]
    float (*Ps)[128] = (float(*)[128])(sm + PS_F);   // [128][128] row-major

    const int tid = threadIdx.x;
    const int tx = tid & 15, ty = tid >> 4;
    const int bh = blockIdx.y;
    const int b = bh / NH, h = bh - b * NH;
    const int q0 = blockIdx.x << 7;

    const float* qb = q + (size_t)b * SQ * DM + (size_t)h * DKH;
    const float* kb = k + (size_t)b * SQ * DM + (size_t)h * DKH;
    const float* vb = v + (size_t)b * SQ * DM + (size_t)h * DKH;
    float* ob       = o + (size_t)b * SQ * DM + (size_t)h * DKH;

    const int lr = tid >> 4;          // 0..15
    const int lc = (tid & 15) << 2;   // 0..60

    // Load Q tile (128 x 64) transposed, pre-scaled by 1/sqrt(64)
    #pragma unroll
    for (int it = 0; it < 8; it++) {
        int r = lr + it * 16;
        float4 t = *(const float4*)(qb + (size_t)(q0 + r) * DM + lc);
        Qs[lc + 0][r] = t.x * 0.125f;
        Qs[lc + 1][r] = t.y * 0.125f;
        Qs[lc + 2][r] = t.z * 0.125f;
        Qs[lc + 3][r] = t.w * 0.125f;
    }

    float m_i[8], l_i[8], oacc[8][4];
    #pragma unroll
    for (int i = 0; i < 8; i++) {
        m_i[i] = -1e30f; l_i[i] = 0.f;
        oacc[i][0] = oacc[i][1] = oacc[i][2] = oacc[i][3] = 0.f;
    }

    for (int kv0 = 0; kv0 < SQ; kv0 += 128) {
        __syncthreads();   // previous iteration's readers of Ks/Vs/Ps done
        #pragma unroll
        for (int it = 0; it < 8; it++) {
            int r = lr + it * 16;
            float4 tk = *(const float4*)(kb + (size_t)(kv0 + r) * DM + lc);
            Ks[lc + 0][r] = tk.x; Ks[lc + 1][r] = tk.y;
            Ks[lc + 2][r] = tk.z; Ks[lc + 3][r] = tk.w;
            float4 tv = *(const float4*)(vb + (size_t)(kv0 + r) * DM + lc);
            *(float4*)&Vs[r][lc] = tv;
        }
        __syncthreads();

        // S = Q K^T (scaled). s[i][j]: row ty*8+i, col tx*4+j (j<4) / 64+tx*4+j-4
        float s[8][8] = {};
        #pragma unroll 4
        for (int d = 0; d < 64; d++) {
            float4 fa0 = *(const float4*)&Qs[d][ty << 3];
            float4 fa1 = *(const float4*)&Qs[d][(ty << 3) + 4];
            float4 fb0 = *(const float4*)&Ks[d][tx << 2];
            float4 fb1 = *(const float4*)&Ks[d][64 + (tx << 2)];
            float a[8]  = {fa0.x, fa0.y, fa0.z, fa0.w, fa1.x, fa1.y, fa1.z, fa1.w};
            float bb[8] = {fb0.x, fb0.y, fb0.z, fb0.w, fb1.x, fb1.y, fb1.z, fb1.w};
            #pragma unroll
            for (int i = 0; i < 8; i++)
                #pragma unroll
                for (int j = 0; j < 8; j++)
                    s[i][j] = fmaf(a[i], bb[j], s[i][j]);
        }

        // Online softmax (row groups live in half-warps: same ty, tx=0..15)
        #pragma unroll
        for (int i = 0; i < 8; i++) {
            float mx = fmaxf(fmaxf(fmaxf(s[i][0], s[i][1]), fmaxf(s[i][2], s[i][3])),
                             fmaxf(fmaxf(s[i][4], s[i][5]), fmaxf(s[i][6], s[i][7])));
            mx = redmax16(mx);
            float mnew = fmaxf(m_i[i], mx);
            float alpha = __expf(m_i[i] - mnew);
            m_i[i] = mnew;
            float rsum = 0.f;
            #pragma unroll
            for (int j = 0; j < 8; j++) {
                float p = __expf(s[i][j] - mnew);
                s[i][j] = p;
                rsum += p;
            }
            rsum = redsum16(rsum);
            l_i[i] = l_i[i] * alpha + rsum;
            oacc[i][0] *= alpha; oacc[i][1] *= alpha;
            oacc[i][2] *= alpha; oacc[i][3] *= alpha;
        }

        // Store P row-major (conflict-free float4 stores: 16 consecutive groups)
        #pragma unroll
        for (int i = 0; i < 8; i++) {
            int r = (ty << 3) + i;
            float4 p0, p1;
            p0.x = s[i][0]; p0.y = s[i][1]; p0.z = s[i][2]; p0.w = s[i][3];
            p1.x = s[i][4]; p1.y = s[i][5]; p1.z = s[i][6]; p1.w = s[i][7];
            *(float4*)&Ps[r][tx << 2] = p0;
            *(float4*)&Ps[r][64 + (tx << 2)] = p1;
        }
        __syncthreads();

        // O += P V : per thread rows ty*8+i, d-cols tx*4..+3.
        // P loads broadcast across tx; V loads minimum-wavefront.
        for (int c4 = 0; c4 < 128; c4 += 4) {
            float4 vv0 = *(const float4*)&Vs[c4 + 0][tx << 2];
            float4 vv1 = *(const float4*)&Vs[c4 + 1][tx << 2];
            float4 vv2 = *(const float4*)&Vs[c4 + 2][tx << 2];
            float4 vv3 = *(const float4*)&Vs[c4 + 3][tx << 2];
            #pragma unroll
            for (int i = 0; i < 8; i++) {
                float4 p4 = *(const float4*)&Ps[(ty << 3) + i][c4];
                oacc[i][0] = fmaf(p4.x, vv0.x, oacc[i][0]);
                oacc[i][1] = fmaf(p4.x, vv0.y, oacc[i][1]);
                oacc[i][2] = fmaf(p4.x, vv0.z, oacc[i][2]);
                oacc[i][3] = fmaf(p4.x, vv0.w, oacc[i][3]);
                oacc[i][0] = fmaf(p4.y, vv1.x, oacc[i][0]);
                oacc[i][1] = fmaf(p4.y, vv1.y, oacc[i][1]);
                oacc[i][2] = fmaf(p4.y, vv1.z, oacc[i][2]);
                oacc[i][3] = fmaf(p4.y, vv1.w, oacc[i][3]);
                oacc[i][0] = fmaf(p4.z, vv2.x, oacc[i][0]);
                oacc[i][1] = fmaf(p4.z, vv2.y, oacc[i][1]);
                oacc[i][2] = fmaf(p4.z, vv2.z, oacc[i][2]);
                oacc[i][3] = fmaf(p4.z, vv2.w, oacc[i][3]);
                oacc[i][0] = fmaf(p4.w, vv3.x, oacc[i][0]);
                oacc[i][1] = fmaf(p4.w, vv3.y, oacc[i][1]);
                oacc[i][2] = fmaf(p4.w, vv3.z, oacc[i][2]);
                oacc[i][3] = fmaf(p4.w, vv3.w, oacc[i][3]);
            }
        }
    }

    // Normalize + write combined layout (B,S,H*dk) directly
    #pragma unroll
    for (int i = 0; i < 8; i++) {
        float inv = 1.0f / l_i[i];
        float4 r;
        r.x = oacc[i][0] * inv; r.y = oacc[i][1] * inv;
        r.z = oacc[i][2] * inv; r.w = oacc[i][3] * inv;
        *(float4*)(ob + (size_t)(q0 + (ty << 3) + i) * DM + (tx << 2)) = r;
    }
}

// ---------------------------------------------------------------------------
extern "C" void kernel_launch(void* const* d_in, const int* in_sizes, int n_in,
                              void* d_out, int out_size)
{
    const float* Q  = (const float*)d_in[0];
    const float* K  = (const float*)d_in[1];
    const float* V  = (const float*)d_in[2];
    const float* Wq = (const float*)d_in[3];
    const float* bq = (const float*)d_in[4];
    const float* Wk = (const float*)d_in[5];
    const float* bk = (const float*)d_in[6];
    const float* Wv = (const float*)d_in[7];
    const float* bv = (const float*)d_in[8];
    const float* Wo = (const float*)d_in[9];
    const float* bo = (const float*)d_in[10];
    float* out = (float*)d_out;

    float *gq, *gk, *gv, *ga;
    cudaGetSymbolAddress((void**)&gq, g_q);
    cudaGetSymbolAddress((void**)&gk, g_k);
    cudaGetSymbolAddress((void**)&gv, g_v);
    cudaGetSymbolAddress((void**)&ga, g_att);

    cudaFuncSetAttribute(flash_kernel,
                         cudaFuncAttributeMaxDynamicSharedMemorySize, FL_SMEM);

    dim3 gg(DM / 128, NT / 128);   // (6, 64)
    gemm_bias_kernel<<<gg, 256>>>(Q, Wq, bq, gq);
    gemm_bias_kernel<<<gg, 256>>>(K, Wk, bk, gk);
    gemm_bias_kernel<<<gg, 256>>>(V, Wv, bv, gv);

    dim3 fg(SQ / 128, NB * NH);    // (32, 24)
    flash_kernel<<<fg, 256, FL_SMEM>>>(gq, gk, gv, ga);

    gemm_bias_kernel<<<gg, 256>>>(ga, Wo, bo, out);
}